// round 15
// baseline (speedup 1.0000x reference)
#include <cuda_runtime.h>
#include <cuda_fp16.h>
#include <math.h>
#include <stdint.h>

#define NN    30000
#define DMAXN 16
#define INF   128
#define HIDF  256

typedef uint32_t u32;

// ---------------- fp16 / async helpers ---------------------------------------
// packed-word layout per 16-k chunk (8 u32 words): word w even: k={w,w+1};
// w odd: k={w+7,w+8}. One LDS.64 per fragment row.
__device__ __forceinline__ u32 packh2(float lo, float hi) {
    u32 r;
    asm("{ .reg .f16 l, h; cvt.rn.f16.f32 l, %1; cvt.rn.f16.f32 h, %2;"
        " mov.b32 %0, {l, h}; }" : "=r"(r) : "f"(lo), "f"(hi));
    return r;
}
__device__ __forceinline__ void mma16(float* d, u32 a0, u32 a1, u32 a2, u32 a3,
                                      u32 b0, u32 b1) {
    asm volatile("mma.sync.aligned.m16n8k16.row.col.f32.f16.f16.f32 "
                 "{%0,%1,%2,%3}, {%4,%5,%6,%7}, {%8,%9}, {%0,%1,%2,%3};"
                 : "+f"(d[0]), "+f"(d[1]), "+f"(d[2]), "+f"(d[3])
                 : "r"(a0), "r"(a1), "r"(a2), "r"(a3), "r"(b0), "r"(b1));
}
__device__ __forceinline__ u32 smem_u32(const void* p) {
    return (u32)__cvta_generic_to_shared(p);
}
__device__ __forceinline__ void cpa16(u32 d, const void* s) {
    asm volatile("cp.async.cg.shared.global [%0], [%1], 16;" :: "r"(d), "l"(s));
}
__device__ __forceinline__ void cpa_commit() {
    asm volatile("cp.async.commit_group;");
}
template <int N> __device__ __forceinline__ void cpa_wait() {
    asm volatile("cp.async.wait_group %0;" :: "n"(N));
}
__device__ __forceinline__ float sigmoid_f(float x) {
    return __fdividef(1.f, 1.f + __expf(-x));
}
__device__ __forceinline__ float tanh_f(float x) {
    float ax = fabsf(x);
    float e = __expf(-2.f * ax);
    return copysignf(__fdividef(1.f - e, 1.f + e), x);
}

// ---------------- scratch (device globals) -----------------------------------
__device__ u32   d_featq[NN * INF / 2];
__device__ u32   d_houtq[NN * HIDF / 2];
__device__ u32   d_hfin1[NN * INF / 2];    // final LSTM1 hidden (sorted rows)
__device__ u32   d_hfin2[NN * HIDF / 2];
__device__ float d_c1[NN * INF];           // written at t=0 before any read
__device__ float d_c2[NN * HIDF];
__device__ float d_gx1[NN * 4 * INF];
__device__ float d_gx2[NN * 4 * HIDF];
__device__ u32   d_Wih1q[4 * INF * INF / 2];
__device__ u32   d_Whh1q[4 * INF * INF / 2];
__device__ u32   d_Wih2q[4 * HIDF * HIDF / 2];
__device__ u32   d_Whh2q[4 * HIDF * HIDF / 2];
__device__ u32   d_Ws1q[HIDF * INF / 2];
__device__ u32   d_Wn1q[HIDF * INF / 2];
__device__ u32   d_Ws2q[64 * HIDF / 2];
__device__ u32   d_Wn2q[64 * HIDF / 2];
__device__ int   d_perm[NN];
__device__ int   d_rank[NN];
__device__ int   d_cnt[DMAXN + 2];
__device__ int   d_ofs[DMAXN + 2];
__device__ int   d_Kt[DMAXN + 1];

// ---------------- counting sort by degree (descending) ----------------------
__global__ void sort_zero_k() {
    if (threadIdx.x < DMAXN + 2) d_cnt[threadIdx.x] = 0;
}
__global__ void sort_hist_k(const int* __restrict__ deg, int n) {
    int i = blockIdx.x * blockDim.x + threadIdx.x;
    if (i < n) atomicAdd(&d_cnt[deg[i]], 1);
}
__global__ void sort_scan_k() {
    int ofs[DMAXN + 2];
    int run = 0;
    for (int d = DMAXN; d >= 1; --d) { ofs[d] = run; run += d_cnt[d]; }
    for (int d = 1; d <= DMAXN; ++d) d_ofs[d] = ofs[d];
    for (int t = 0; t < DMAXN; ++t) d_Kt[t] = ofs[t + 1] + d_cnt[t + 1];
}
__global__ void sort_scatter_k(const int* __restrict__ deg, int n) {
    int i = blockIdx.x * blockDim.x + threadIdx.x;
    if (i < n) {
        int p = atomicAdd(&d_ofs[deg[i]], 1);
        d_perm[p] = i;
        d_rank[i] = p;
    }
}

// ---------------- fp32 -> fp16 packed-word layout, all operands --------------
__global__ void convert_all_k(const float* s0, int n0, const float* s1, int n1,
                              const float* s2, int n2, const float* s3, int n3,
                              const float* s4, int n4, const float* s5, int n5,
                              const float* s6, int n6, const float* s7, int n7,
                              const float* s8, int n8)
{
    const float* srcs[9] = {s0, s1, s2, s3, s4, s5, s6, s7, s8};
    u32* dsts[9] = {d_featq, d_Wih1q, d_Whh1q, d_Wih2q, d_Whh2q,
                    d_Ws1q, d_Wn1q, d_Ws2q, d_Wn2q};
    int lens[9] = {n0 / 2, n1 / 2, n2 / 2, n3 / 2, n4 / 2,
                   n5 / 2, n6 / 2, n7 / 2, n8 / 2};
    int total = 0;
#pragma unroll
    for (int s = 0; s < 9; s++) total += lens[s];

    const int stride = gridDim.x * blockDim.x;
    for (int g = blockIdx.x * blockDim.x + threadIdx.x; g < total; g += stride) {
        int i = g, s = 0;
#pragma unroll
        for (int j = 0; j < 8; j++)
            if (i >= lens[s]) { i -= lens[s]; s++; }
        const int w = i & 7;
        const int k0 = (w & 1) ? (w + 7) : w;
        const int base = ((i >> 3) << 4) + k0;
        dsts[s][i] = packh2(srcs[s][base], srcs[s][base + 1]);
    }
}

// ---------------- shared mma tile: warp grid 2(M) x 4(N), fp16 k16 -----------
template <int NFRW>
__device__ __forceinline__ void mma_tile(const u32 (*__restrict__ As)[8],
                                         const u32 (*__restrict__ Bs)[8],
                                         float (*acc)[NFRW][4],
                                         int wm, int wn, int q, int tig)
{
    uint2 bv[NFRW];
#pragma unroll
    for (int nf = 0; nf < NFRW; nf++)
        bv[nf] = *(const uint2*)&Bs[wn * (8 * NFRW) + nf * 8 + q][2 * tig];
#pragma unroll
    for (int mf = 0; mf < 4; mf++) {
        const uint2 alo = *(const uint2*)&As[wm * 64 + mf * 16 + q][2 * tig];
        const uint2 ahi = *(const uint2*)&As[wm * 64 + mf * 16 + q + 8][2 * tig];
#pragma unroll
        for (int nf = 0; nf < NFRW; nf++)
            mma16(acc[mf][nf], alo.x, ahi.x, alo.y, ahi.y, bv[nf].x, bv[nf].y);
    }
}

// ============================================================================
// gx = A @ W^T + (bih+bhh)
// ============================================================================
template <int K, int SRC>
__global__ __launch_bounds__(256, 2)
void mma_gx_k(const float* __restrict__ bih, const float* __restrict__ bhh, int n)
{
    const int r0 = blockIdx.x * 128;
    if (r0 >= n) return;
    const int n0 = blockIdx.y * 128;
    constexpr int NCH = K / 16;
    constexpr int KW = K / 2;
    constexpr int M4 = 4 * K;

    __shared__ __align__(16) u32 As[4][128][8];
    __shared__ __align__(16) u32 Bs[4][128][8];
    constexpr u32 BUFSZ = 128 * 8 * 4;

    const u32* A  = (SRC == 1) ? d_featq : d_houtq;
    const u32* Wq = (SRC == 1) ? d_Wih1q : d_Wih2q;
    float* out    = (SRC == 1) ? d_gx1 : d_gx2;

    const int tid = threadIdx.x;
    const int w = tid >> 5, lane = tid & 31;
    const int q = lane >> 2, tig = lane & 3;
    const int wm = w >> 2, wn = w & 3;

    const int crow = tid >> 1;
    const int cseg = (tid & 1) * 4;
    int ra = r0 + crow; if (ra > n - 1) ra = n - 1;
    const u32* pa = A + (size_t)ra * KW + cseg;
    const u32* pb = Wq + (size_t)(n0 + crow) * KW + cseg;

    const u32 asm0 = smem_u32(&As[0][crow][cseg]);
    const u32 bsm0 = smem_u32(&Bs[0][crow][cseg]);

    float acc[4][4][4];
#pragma unroll
    for (int i = 0; i < 4; i++)
#pragma unroll
        for (int j = 0; j < 4; j++)
#pragma unroll
            for (int c = 0; c < 4; c++) acc[i][j][c] = 0.f;

    auto issue = [&](int chunk) {
        if (chunk < NCH) {
            const u32 off = (chunk & 3) * BUFSZ;
            cpa16(asm0 + off, pa + chunk * 8);
            cpa16(bsm0 + off, pb + chunk * 8);
        }
        cpa_commit();
    };
    issue(0); issue(1); issue(2);

#pragma unroll 1
    for (int c = 0; c < NCH; c++) {
        cpa_wait<2>();
        __syncthreads();
        issue(c + 3);
        mma_tile<4>(As[c & 3], Bs[c & 3], acc, wm, wn, q, tig);
    }

    float2 bsum[4];
#pragma unroll
    for (int nf = 0; nf < 4; nf++) {
        const int col = n0 + wn * 32 + nf * 8 + 2 * tig;
        bsum[nf] = make_float2(bih[col] + bhh[col], bih[col + 1] + bhh[col + 1]);
    }
#pragma unroll
    for (int mf = 0; mf < 4; mf++)
#pragma unroll
        for (int half = 0; half < 2; half++) {
            const int r = r0 + wm * 64 + mf * 16 + q + half * 8;
            if (r >= n) continue;
#pragma unroll
            for (int nf = 0; nf < 4; nf++) {
                const int col = n0 + wn * 32 + nf * 8 + 2 * tig;
                *(float2*)(out + (size_t)r * M4 + col) =
                    make_float2(acc[mf][nf][half * 2]     + bsum[nf].x,
                                acc[mf][nf][half * 2 + 1] + bsum[nf].y);
            }
        }
}

// ============================================================================
// Persistent fused LSTM (one launch per layer). Block owns 128 sorted rows,
// loops t and all N-slices; h lives in smem (double-buffered, fragment-word
// layout == GEMM A operand). B streamed via t-invariant 4-deep cp.async ring.
// Final h -> d_hfin (buffer chosen by deg parity per row).
// ============================================================================
template <int H, int LAYER>
__global__ __launch_bounds__(256)
void fused_lstm_k(const int* __restrict__ nbr_idx,
                  const int* __restrict__ deg_g, int n)
{
    constexpr int NCH = H / 16;     // k-chunks per slice GEMM
    constexpr int NSL = H / 32;     // 32-cell slices
    constexpr int HW  = H / 2;      // u32 words per h row
    constexpr int TOT = NSL * NCH;  // flattened chunks per step (TOT % 4 == 0)
    constexpr u32 BS_BUF = 128 * 8 * 4;

    extern __shared__ __align__(16) u32 sm[];
    u32* hs    = sm;                          // [2][NCH][128][8]
    u32* bs    = sm + 2 * NCH * 1024;         // [4][128][8]
    int* s_nbr = (int*)(bs + 4096);           // [16][128]
    int* s_deg = s_nbr + DMAXN * 128;         // [128]
    int* s_node = s_deg + 128;                // [128]

    const float* gx = (LAYER == 1) ? d_gx1 : d_gx2;
    float*      cst = (LAYER == 1) ? d_c1 : d_c2;
    const u32*  Wq  = (LAYER == 1) ? d_Whh1q : d_Whh2q;
    u32*       hfin = (LAYER == 1) ? d_hfin1 : d_hfin2;

    const int r0 = blockIdx.x * 128;
    if (r0 >= n) return;
    const int tid = threadIdx.x;
    const int w = tid >> 5, lane = tid & 31;
    const int q = lane >> 2, tig = lane & 3;
    const int wm = w >> 2, wn = w & 3;

    // ---- upfront: perm/deg, then all 16 neighbor columns ----
    if (tid < 128) {
        int r = r0 + tid; if (r > n - 1) r = n - 1;
        const int node = d_perm[r];
        s_node[tid] = node;
        s_deg[tid] = deg_g[node];
    }
    __syncthreads();
    for (int l = tid; l < 128 * DMAXN; l += 256) {
        const int row = l >> 4, t = l & 15;
        s_nbr[t * 128 + row] = nbr_idx[s_node[row] * DMAXN + t];
    }

    // ---- B cp.async ring (t-invariant addresses) ----
    const int crow = tid >> 1;
    const int cseg = (tid & 1) * 4;
    const u32 bsm0 = smem_u32(&bs[crow * 8 + cseg]);
    auto issue = [&](int cc) {
        const int sl = cc / NCH, ch = cc & (NCH - 1);
        const int wr = ((crow >> 3) & 3) * H + sl * 32 + (crow & 7)
                     + ((crow >> 5) << 3);
        cpa16(bsm0 + (u32)(cc & 3) * BS_BUF,
              Wq + (size_t)wr * HW + ch * 8 + cseg);
        cpa_commit();
    };

    float acc[4][4][4];
#pragma unroll
    for (int i = 0; i < 4; i++)
#pragma unroll
        for (int j = 0; j < 4; j++)
#pragma unroll
            for (int c = 0; c < 4; c++) acc[i][j][c] = 0.f;

    // ---- fused cell epilogue for slice sl at step t ----
    auto do_epi = [&](int t, int sl) {
        const int Kt = d_Kt[t];
        const int jc = sl * 32 + wn * 8 + 2 * tig;
        const int jm = jc & 15;
        const int hw = (jm < 8) ? jm : jm - 7;
        const int jch = jc >> 4;
        const int wb = (t + 1) & 1;
#pragma unroll
        for (int mf = 0; mf < 4; mf++)
#pragma unroll
            for (int half = 0; half < 2; half++) {
                const int lr = wm * 64 + mf * 16 + q + half * 8;
                const int r = r0 + lr;
                if (r >= Kt) continue;
                const int nbr = s_nbr[t * 128 + lr];
                const float* gp = gx + (size_t)nbr * (4 * H) + jc;
                const float2 gI = *(const float2*)(gp);
                const float2 gF = *(const float2*)(gp + H);
                const float2 gG = *(const float2*)(gp + 2 * H);
                const float2 gO = *(const float2*)(gp + 3 * H);
                float2 cold = make_float2(0.f, 0.f);
                if (t > 0) cold = *(const float2*)(cst + (size_t)r * H + jc);
                float cn[2], hn[2];
#pragma unroll
                for (int b = 0; b < 2; b++) {
                    const float gi = acc[mf][0][half * 2 + b] + (b ? gI.y : gI.x);
                    const float gf = acc[mf][1][half * 2 + b] + (b ? gF.y : gF.x);
                    const float gg = acc[mf][2][half * 2 + b] + (b ? gG.y : gG.x);
                    const float go = acc[mf][3][half * 2 + b] + (b ? gO.y : gO.x);
                    const float cv = sigmoid_f(gf) * (b ? cold.y : cold.x)
                                   + sigmoid_f(gi) * tanh_f(gg);
                    cn[b] = cv;
                    hn[b] = sigmoid_f(go) * tanh_f(cv);
                }
                *(float2*)(cst + (size_t)r * H + jc) = make_float2(cn[0], cn[1]);
                hs[wb * (NCH * 1024) + jch * 1024 + lr * 8 + hw] =
                    packh2(hn[0], hn[1]);
            }
    };

    __syncthreads();   // s_nbr ready

    // ---- t = 0: epilogue only (h0 == 0, c not read); acc is zero ----
#pragma unroll
    for (int sl = 0; sl < NSL; sl++) do_epi(0, sl);

    // ---- pipeline prologue ----
    issue(0); issue(1); issue(2);

    // ---- t >= 1: flattened (slice, chunk) loop, seamless ring ----
#pragma unroll 1
    for (int t = 1; t < DMAXN; t++) {
        if (r0 >= d_Kt[t]) break;
        const u32* Ab = hs + (t & 1) * (NCH * 1024);
#pragma unroll 1
        for (int cc = 0; cc < TOT; cc++) {
            cpa_wait<2>();
            __syncthreads();
            issue((cc + 3) & (TOT - 1));
            const int ch = cc & (NCH - 1);
            if (ch == 0) {
#pragma unroll
                for (int i = 0; i < 4; i++)
#pragma unroll
                    for (int j = 0; j < 4; j++)
#pragma unroll
                        for (int c = 0; c < 4; c++) acc[i][j][c] = 0.f;
            }
            mma_tile<4>((const u32(*)[8])(Ab + ch * 1024),
                        (const u32(*)[8])(bs + (cc & 3) * 1024),
                        acc, wm, wn, q, tig);
            if (ch == NCH - 1) do_epi(t, cc / NCH);
        }
    }

    cpa_wait<0>();
    __syncthreads();

    // ---- final h -> global (buffer by deg parity per row) ----
    for (int idx = tid; idx < 128 * HW; idx += 256) {
        const int row = idx / HW, word = idx % HW;
        const int r = r0 + row;
        if (r < n)
            hfin[(size_t)r * HW + word] =
                hs[(s_deg[row] & 1) * (NCH * 1024) + (word >> 3) * 1024
                   + row * 8 + (word & 7)];
    }
}

// ============================================================================
// Fused FC: out = act(A1 @ W1^T + hfin @ W2^T + b), K = K1+K2 concat.
// ============================================================================
template <int K1, int K2, int NOUT, int BLKN, int LAYER>
__global__ __launch_bounds__(256, 2)
void mma_fc_k(const float* __restrict__ bias, float* __restrict__ outp, int n)
{
    const int r0 = blockIdx.x * 128;
    if (r0 >= n) return;
    const int n0 = blockIdx.y * BLKN;
    constexpr int NCH = (K1 + K2) / 16;
    constexpr int NCH1 = K1 / 16;
    constexpr int NFRW = BLKN / 32;
    constexpr int K1W = K1 / 2, K2W = K2 / 2;

    __shared__ __align__(16) u32 As[4][128][8];
    __shared__ __align__(16) u32 Bs[4][BLKN][8];
    constexpr u32 BUFSZ_A = 128 * 8 * 4;
    constexpr u32 BUFSZ_B = BLKN * 8 * 4;

    const u32* A1 = (LAYER == 1) ? d_featq : d_houtq;
    const u32* HB = (LAYER == 1) ? d_hfin1 : d_hfin2;
    const u32* W1 = (LAYER == 1) ? d_Ws1q : d_Ws2q;
    const u32* W2 = (LAYER == 1) ? d_Wn1q : d_Wn2q;

    const int tid = threadIdx.x;
    const int w = tid >> 5, lane = tid & 31;
    const int q = lane >> 2, tig = lane & 3;
    const int wm = w >> 2, wn = w & 3;

    const int crow = tid >> 1;
    const int cseg = (tid & 1) * 4;
    int ra = r0 + crow; if (ra > n - 1) ra = n - 1;
    const u32* p1 = A1 + (size_t)ra * K1W + cseg;
    const u32* p2 = HB + (size_t)d_rank[ra] * K2W + cseg;
    const bool bact = (tid < 2 * BLKN);
    const int bro = n0 + (crow & (BLKN - 1));
    const u32* q1 = W1 + (size_t)bro * K1W + cseg;
    const u32* q2 = W2 + (size_t)bro * K2W + cseg;

    const u32 asm0 = smem_u32(&As[0][crow][cseg]);
    const u32 bsm0 = smem_u32(&Bs[0][crow & (BLKN - 1)][cseg]);

    float acc[4][NFRW][4];
#pragma unroll
    for (int i = 0; i < 4; i++)
#pragma unroll
        for (int j = 0; j < NFRW; j++)
#pragma unroll
            for (int c = 0; c < 4; c++) acc[i][j][c] = 0.f;

    auto issue = [&](int chunk) {
        if (chunk < NCH) {
            const u32 offA = (chunk & 3) * BUFSZ_A;
            const u32 offB = (chunk & 3) * BUFSZ_B;
            const u32* srcA = (chunk < NCH1) ? (p1 + chunk * 8)
                                             : (p2 + (chunk - NCH1) * 8);
            cpa16(asm0 + offA, srcA);
            if (bact) {
                const u32* srcB = (chunk < NCH1) ? (q1 + chunk * 8)
                                                 : (q2 + (chunk - NCH1) * 8);
                cpa16(bsm0 + offB, srcB);
            }
        }
        cpa_commit();
    };
    issue(0); issue(1); issue(2);

#pragma unroll 1
    for (int c = 0; c < NCH; c++) {
        cpa_wait<2>();
        __syncthreads();
        issue(c + 3);
        mma_tile<NFRW>(As[c & 3], Bs[c & 3], acc, wm, wn, q, tig);
    }

    float2 bv2[NFRW];
#pragma unroll
    for (int nf = 0; nf < NFRW; nf++) {
        const int col = n0 + wn * (8 * NFRW) + nf * 8 + 2 * tig;
        bv2[nf] = make_float2(bias[col], bias[col + 1]);
    }
#pragma unroll
    for (int mf = 0; mf < 4; mf++)
#pragma unroll
        for (int half = 0; half < 2; half++) {
            const int r = r0 + wm * 64 + mf * 16 + q + half * 8;
            if (r >= n) continue;
#pragma unroll
            for (int nf = 0; nf < NFRW; nf++) {
                const int col = n0 + wn * (8 * NFRW) + nf * 8 + 2 * tig;
                float v0 = acc[mf][nf][half * 2]     + bv2[nf].x;
                float v1 = acc[mf][nf][half * 2 + 1] + bv2[nf].y;
                if (LAYER == 1) {
                    v0 = fmaxf(v0, 0.f); v1 = fmaxf(v1, 0.f);
                    const int cm = col & 15;
                    const int cw = (cm < 8) ? cm : cm - 7;
                    d_houtq[(size_t)r * (NOUT / 2) + ((col >> 4) << 3) + cw] =
                        packh2(v0, v1);
                } else {
                    *(float2*)(outp + (size_t)r * NOUT + col) = make_float2(v0, v1);
                }
            }
        }
}

// ---------------- launch ----------------------------------------------------
extern "C" void kernel_launch(void* const* d_in, const int* in_sizes, int n_in,
                              void* d_out, int out_size)
{
    const float* feat    = (const float*)d_in[0];
    const int*   nbr     = (const int*)d_in[1];
    const int*   deg     = (const int*)d_in[2];
    const float* Wih1    = (const float*)d_in[3];
    const float* Whh1    = (const float*)d_in[4];
    const float* bih1    = (const float*)d_in[5];
    const float* bhh1    = (const float*)d_in[6];
    const float* Wself1  = (const float*)d_in[7];
    const float* Wneigh1 = (const float*)d_in[8];
    const float* b1      = (const float*)d_in[9];
    const float* Wih2    = (const float*)d_in[10];
    const float* Whh2    = (const float*)d_in[11];
    const float* bih2    = (const float*)d_in[12];
    const float* bhh2    = (const float*)d_in[13];
    const float* Wself2  = (const float*)d_in[14];
    const float* Wneigh2 = (const float*)d_in[15];
    const float* b2      = (const float*)d_in[16];

    const int n  = in_sizes[2];           // = N
    const int rb = (n + 127) / 128;

    // dynamic smem sizes for fused LSTM kernels
    const int smem1 = (2 * (INF / 16) * 1024 + 4096 + DMAXN * 128 + 256) * 4;
    const int smem2 = (2 * (HIDF / 16) * 1024 + 4096 + DMAXN * 128 + 256) * 4;
    cudaFuncSetAttribute(fused_lstm_k<INF, 1>,
                         cudaFuncAttributeMaxDynamicSharedMemorySize, smem1);
    cudaFuncSetAttribute(fused_lstm_k<HIDF, 2>,
                         cudaFuncAttributeMaxDynamicSharedMemorySize, smem2);

    sort_zero_k<<<1, 32>>>();
    sort_hist_k<<<(n + 255) / 256, 256>>>(deg, n);
    sort_scan_k<<<1, 1>>>();
    sort_scatter_k<<<(n + 255) / 256, 256>>>(deg, n);

    convert_all_k<<<1024, 256>>>(feat, in_sizes[0], Wih1, in_sizes[3],
                                 Whh1, in_sizes[4], Wih2, in_sizes[10],
                                 Whh2, in_sizes[11], Wself1, in_sizes[7],
                                 Wneigh1, in_sizes[8], Wself2, in_sizes[14],
                                 Wneigh2, in_sizes[15]);

    // layer 1
    mma_gx_k<128, 1><<<dim3(rb, 4), 256>>>(bih1, bhh1, n);
    fused_lstm_k<INF, 1><<<rb, 256, smem1>>>(nbr, deg, n);
    mma_fc_k<128, 128, 256, 128, 1><<<dim3(rb, 2), 256>>>(b1, nullptr, n);

    // layer 2
    mma_gx_k<256, 2><<<dim3(rb, 8), 256>>>(bih2, bhh2, n);
    fused_lstm_k<HIDF, 2><<<rb, 256, smem2>>>(nbr, deg, n);
    mma_fc_k<256, 256, 64, 64, 2><<<dim3(rb, 1), 256>>>(b2, (float*)d_out, n);
}

// round 16
// speedup vs baseline: 1.4649x; 1.4649x over previous
#include <cuda_runtime.h>
#include <cuda_fp16.h>
#include <math.h>
#include <stdint.h>

#define NN    30000
#define DMAXN 16
#define INF   128
#define HIDF  256

typedef uint32_t u32;

// ---------------- fp16 / async helpers ---------------------------------------
// packed-word layout per 16-k chunk (8 u32 words): word w even: k={w,w+1};
// w odd: k={w+7,w+8}. One LDS.64 per fragment row.
__device__ __forceinline__ u32 packh2(float lo, float hi) {
    u32 r;
    asm("{ .reg .f16 l, h; cvt.rn.f16.f32 l, %1; cvt.rn.f16.f32 h, %2;"
        " mov.b32 %0, {l, h}; }" : "=r"(r) : "f"(lo), "f"(hi));
    return r;
}
__device__ __forceinline__ void mma16(float* d, u32 a0, u32 a1, u32 a2, u32 a3,
                                      u32 b0, u32 b1) {
    asm volatile("mma.sync.aligned.m16n8k16.row.col.f32.f16.f16.f32 "
                 "{%0,%1,%2,%3}, {%4,%5,%6,%7}, {%8,%9}, {%0,%1,%2,%3};"
                 : "+f"(d[0]), "+f"(d[1]), "+f"(d[2]), "+f"(d[3])
                 : "r"(a0), "r"(a1), "r"(a2), "r"(a3), "r"(b0), "r"(b1));
}
__device__ __forceinline__ u32 smem_u32(const void* p) {
    return (u32)__cvta_generic_to_shared(p);
}
__device__ __forceinline__ void cpa16(u32 d, const void* s) {
    asm volatile("cp.async.cg.shared.global [%0], [%1], 16;" :: "r"(d), "l"(s));
}
__device__ __forceinline__ void cpa_commit() {
    asm volatile("cp.async.commit_group;");
}
template <int N> __device__ __forceinline__ void cpa_wait() {
    asm volatile("cp.async.wait_group %0;" :: "n"(N));
}
__device__ __forceinline__ float sigmoid_f(float x) {
    return __fdividef(1.f, 1.f + __expf(-x));
}
__device__ __forceinline__ float tanh_f(float x) {
    float ax = fabsf(x);
    float e = __expf(-2.f * ax);
    return copysignf(__fdividef(1.f - e, 1.f + e), x);
}

// ---------------- scratch (device globals) -----------------------------------
__device__ u32   d_featq[NN * INF / 2];
__device__ u32   d_houtq[NN * HIDF / 2];
__device__ u32   d_h1q[2][NN * INF / 2];
__device__ u32   d_h2q[2][NN * HIDF / 2];
__device__ float d_c1[NN * INF];          // written at t=0 before any read
__device__ float d_c2[NN * HIDF];
// gx layout: [node][jpair = j/2][gate 0..3][2]  (gate-interleaved, fp32)
__device__ float d_gx1[NN * 4 * INF];
__device__ float d_gx2[NN * 4 * HIDF];
__device__ u32   d_Wih1q[4 * INF * INF / 2];
__device__ u32   d_Whh1q[4 * INF * INF / 2];
__device__ u32   d_Wih2q[4 * HIDF * HIDF / 2];
__device__ u32   d_Whh2q[4 * HIDF * HIDF / 2];
__device__ u32   d_Ws1q[HIDF * INF / 2];
__device__ u32   d_Wn1q[HIDF * INF / 2];
__device__ u32   d_Ws2q[64 * HIDF / 2];
__device__ u32   d_Wn2q[64 * HIDF / 2];
__device__ int   d_perm[NN];
__device__ int   d_rank[NN];
__device__ int   d_cnt[DMAXN + 2];
__device__ int   d_ofs[DMAXN + 2];
__device__ int   d_Kt[DMAXN + 1];

// ---------------- counting sort by degree (descending) ----------------------
__global__ void sort_zero_k() {
    if (threadIdx.x < DMAXN + 2) d_cnt[threadIdx.x] = 0;
}
__global__ void sort_hist_k(const int* __restrict__ deg, int n) {
    int i = blockIdx.x * blockDim.x + threadIdx.x;
    if (i < n) atomicAdd(&d_cnt[deg[i]], 1);
}
__global__ void sort_scan_k() {
    int ofs[DMAXN + 2];
    int run = 0;
    for (int d = DMAXN; d >= 1; --d) { ofs[d] = run; run += d_cnt[d]; }
    for (int d = 1; d <= DMAXN; ++d) d_ofs[d] = ofs[d];
    for (int t = 0; t < DMAXN; ++t) d_Kt[t] = ofs[t + 1] + d_cnt[t + 1];
}
__global__ void sort_scatter_k(const int* __restrict__ deg, int n) {
    int i = blockIdx.x * blockDim.x + threadIdx.x;
    if (i < n) {
        int p = atomicAdd(&d_ofs[deg[i]], 1);
        d_perm[p] = i;
        d_rank[i] = p;
    }
}

// ---------------- fp32 -> fp16 packed-word layout, all operands --------------
__global__ void convert_all_k(const float* s0, int n0, const float* s1, int n1,
                              const float* s2, int n2, const float* s3, int n3,
                              const float* s4, int n4, const float* s5, int n5,
                              const float* s6, int n6, const float* s7, int n7,
                              const float* s8, int n8)
{
    const float* srcs[9] = {s0, s1, s2, s3, s4, s5, s6, s7, s8};
    u32* dsts[9] = {d_featq, d_Wih1q, d_Whh1q, d_Wih2q, d_Whh2q,
                    d_Ws1q, d_Wn1q, d_Ws2q, d_Wn2q};
    int lens[9] = {n0 / 2, n1 / 2, n2 / 2, n3 / 2, n4 / 2,
                   n5 / 2, n6 / 2, n7 / 2, n8 / 2};
    int total = 0;
#pragma unroll
    for (int s = 0; s < 9; s++) total += lens[s];

    const int stride = gridDim.x * blockDim.x;
    for (int g = blockIdx.x * blockDim.x + threadIdx.x; g < total; g += stride) {
        int i = g, s = 0;
#pragma unroll
        for (int j = 0; j < 8; j++)
            if (i >= lens[s]) { i -= lens[s]; s++; }
        const int w = i & 7;
        const int k0 = (w & 1) ? (w + 7) : w;
        const int base = ((i >> 3) << 4) + k0;
        dsts[s][i] = packh2(srcs[s][base], srcs[s][base + 1]);
    }
}

// ---------------- shared mma tile: warp grid 2(M) x 4(N), fp16 k16 -----------
template <int NFRW>
__device__ __forceinline__ void mma_tile(const u32 (*__restrict__ As)[8],
                                         const u32 (*__restrict__ Bs)[8],
                                         float (*acc)[NFRW][4],
                                         int wm, int wn, int q, int tig)
{
    uint2 bv[NFRW];
#pragma unroll
    for (int nf = 0; nf < NFRW; nf++)
        bv[nf] = *(const uint2*)&Bs[wn * (8 * NFRW) + nf * 8 + q][2 * tig];
#pragma unroll
    for (int mf = 0; mf < 4; mf++) {
        const uint2 alo = *(const uint2*)&As[wm * 64 + mf * 16 + q][2 * tig];
        const uint2 ahi = *(const uint2*)&As[wm * 64 + mf * 16 + q + 8][2 * tig];
#pragma unroll
        for (int nf = 0; nf < NFRW; nf++)
            mma16(acc[mf][nf], alo.x, ahi.x, alo.y, ahi.y, bv[nf].x, bv[nf].y);
    }
}

// ============================================================================
// gx = A @ W^T + (bih+bhh), written gate-interleaved: [r][j/2][gate][2].
// B rows gate-regrouped (same mapping as LSTM kernel) so each thread owns all
// 4 gates of its cells -> dense 2x STG.128 per (mf,half).
// ============================================================================
template <int K, int SRC>
__global__ __launch_bounds__(256, 2)
void mma_gx_k(const float* __restrict__ bih, const float* __restrict__ bhh, int n)
{
    const int r0 = blockIdx.x * 128;
    if (r0 >= n) return;
    const int j0 = blockIdx.y * 32;          // 32 cells x 4 gates per block
    constexpr int NCH = K / 16;
    constexpr int KW = K / 2;
    constexpr int M4 = 4 * K;

    __shared__ __align__(16) u32 As[4][128][8];
    __shared__ __align__(16) u32 Bs[4][128][8];
    constexpr u32 BUFSZ = 128 * 8 * 4;

    const u32* A  = (SRC == 1) ? d_featq : d_houtq;
    const u32* Wq = (SRC == 1) ? d_Wih1q : d_Wih2q;
    float* out    = (SRC == 1) ? d_gx1 : d_gx2;

    const int tid = threadIdx.x;
    const int w = tid >> 5, lane = tid & 31;
    const int q = lane >> 2, tig = lane & 3;
    const int wm = w >> 2, wn = w & 3;

    const int crow = tid >> 1;
    const int cseg = (tid & 1) * 4;
    int ra = r0 + crow; if (ra > n - 1) ra = n - 1;
    const u32* pa = A + (size_t)ra * KW + cseg;
    // gate-regrouped B row: gate=(crow>>3)&3, cell=(crow&7)+8*(crow>>5)
    const int wr = ((crow >> 3) & 3) * K + j0 + (crow & 7) + ((crow >> 5) << 3);
    const u32* pb = Wq + (size_t)wr * KW + cseg;

    const u32 asm0 = smem_u32(&As[0][crow][cseg]);
    const u32 bsm0 = smem_u32(&Bs[0][crow][cseg]);

    float acc[4][4][4];
#pragma unroll
    for (int i = 0; i < 4; i++)
#pragma unroll
        for (int j = 0; j < 4; j++)
#pragma unroll
            for (int c = 0; c < 4; c++) acc[i][j][c] = 0.f;

    auto issue = [&](int chunk) {
        if (chunk < NCH) {
            const u32 off = (chunk & 3) * BUFSZ;
            cpa16(asm0 + off, pa + chunk * 8);
            cpa16(bsm0 + off, pb + chunk * 8);
        }
        cpa_commit();
    };
    issue(0); issue(1); issue(2);

#pragma unroll 1
    for (int c = 0; c < NCH; c++) {
        cpa_wait<2>();
        __syncthreads();
        issue(c + 3);
        mma_tile<4>(As[c & 3], Bs[c & 3], acc, wm, wn, q, tig);
    }

    // biases per [gate][cell-pair]
    const int jc = j0 + wn * 8 + 2 * tig;
    float2 bsum[4];
#pragma unroll
    for (int g = 0; g < 4; g++)
        bsum[g] = make_float2(bih[g * K + jc] + bhh[g * K + jc],
                              bih[g * K + jc + 1] + bhh[g * K + jc + 1]);

#pragma unroll
    for (int mf = 0; mf < 4; mf++)
#pragma unroll
        for (int half = 0; half < 2; half++) {
            const int r = r0 + wm * 64 + mf * 16 + q + half * 8;
            if (r >= n) continue;
            float* op = out + (size_t)r * M4 + ((jc >> 1) << 3);
            *(float4*)(op) = make_float4(
                acc[mf][0][half * 2]     + bsum[0].x,
                acc[mf][0][half * 2 + 1] + bsum[0].y,
                acc[mf][1][half * 2]     + bsum[1].x,
                acc[mf][1][half * 2 + 1] + bsum[1].y);
            *(float4*)(op + 4) = make_float4(
                acc[mf][2][half * 2]     + bsum[2].x,
                acc[mf][2][half * 2 + 1] + bsum[2].y,
                acc[mf][3][half * 2]     + bsum[3].x,
                acc[mf][3][half * 2 + 1] + bsum[3].y);
        }
}

// ============================================================================
// Fused LSTM step: gates = h_{t-1} @ Whh^T + gx[nbr] (biases folded into gx).
// gx gather: two contiguous LDG.128 per (mf,half) -> 100% sector use.
// t==0: GEMM skipped AND c_old not read.
// ============================================================================
template <int H, int LAYER>
__global__ __launch_bounds__(256, 2)
void mma_lstm_k(const int* __restrict__ nbr_idx, int t, int n)
{
    const int Kt = d_Kt[t];
    const int r0 = blockIdx.x * 128;
    if (r0 >= Kt) return;
    const int j0 = blockIdx.y * 32;
    constexpr int NCH = H / 16;
    constexpr int HW = H / 2;

    __shared__ __align__(16) u32 As[4][128][8];
    __shared__ __align__(16) u32 Bs[4][128][8];
    __shared__ int s_nbr[128];
    constexpr u32 BUFSZ = 128 * 8 * 4;

    const float* gx  = (LAYER == 1) ? d_gx1 : d_gx2;
    const u32* hread = (LAYER == 1) ? d_h1q[t & 1] : d_h2q[t & 1];
    u32*      hwrite = (LAYER == 1) ? d_h1q[(t + 1) & 1] : d_h2q[(t + 1) & 1];
    float*    cst    = (LAYER == 1) ? d_c1 : d_c2;
    const u32* Wq    = (LAYER == 1) ? d_Whh1q : d_Whh2q;

    const int tid = threadIdx.x;
    const int w = tid >> 5, lane = tid & 31;
    const int q = lane >> 2, tig = lane & 3;
    const int wm = w >> 2, wn = w & 3;

    if (tid < 128) {
        int r = r0 + tid; if (r > Kt - 1) r = Kt - 1;
        s_nbr[tid] = nbr_idx[d_perm[r] * DMAXN + t];
    }

    float acc[4][4][4];
#pragma unroll
    for (int i = 0; i < 4; i++)
#pragma unroll
        for (int j = 0; j < 4; j++)
#pragma unroll
            for (int c = 0; c < 4; c++) acc[i][j][c] = 0.f;

    if (t > 0) {
        const int crow = tid >> 1;
        const int cseg = (tid & 1) * 4;
        int ra = r0 + crow; if (ra > n - 1) ra = n - 1;
        const u32* pa = hread + (size_t)ra * HW + cseg;
        const int wr = ((crow >> 3) & 3) * H + j0 + (crow & 7) + ((crow >> 5) << 3);
        const u32* pb = Wq + (size_t)wr * HW + cseg;

        const u32 asm0 = smem_u32(&As[0][crow][cseg]);
        const u32 bsm0 = smem_u32(&Bs[0][crow][cseg]);

        auto issue = [&](int chunk) {
            if (chunk < NCH) {
                const u32 off = (chunk & 3) * BUFSZ;
                cpa16(asm0 + off, pa + chunk * 8);
                cpa16(bsm0 + off, pb + chunk * 8);
            }
            cpa_commit();
        };
        issue(0); issue(1); issue(2);

#pragma unroll 1
        for (int c = 0; c < NCH; c++) {
            cpa_wait<2>();
            __syncthreads();
            issue(c + 3);
            mma_tile<4>(As[c & 3], Bs[c & 3], acc, wm, wn, q, tig);
        }
    }
    __syncthreads();

    // ---- fused cell update; gx gate-interleaved ----
    const int jc = j0 + wn * 8 + 2 * tig;
    const int jm = jc & 15;
    const int hw = (jm < 8) ? jm : jm - 7;            // packed word within chunk
    const int hwoff = ((jc >> 4) << 3) + hw;
#pragma unroll
    for (int mf = 0; mf < 4; mf++)
#pragma unroll
        for (int half = 0; half < 2; half++) {
            const int lr = wm * 64 + mf * 16 + q + half * 8;
            const int r = r0 + lr;
            if (r >= Kt) continue;
            const int nbr = s_nbr[lr];
            const float* gp = gx + (size_t)nbr * (4 * H) + ((jc >> 1) << 3);
            const float4 gIF = *(const float4*)(gp);      // gI.x gI.y gF.x gF.y
            const float4 gGO = *(const float4*)(gp + 4);  // gG.x gG.y gO.x gO.y
            float2 cold = make_float2(0.f, 0.f);
            if (t > 0) cold = *(const float2*)(cst + (size_t)r * H + jc);
            float cn[2], hn[2];
#pragma unroll
            for (int b = 0; b < 2; b++) {
                const float gi = acc[mf][0][half * 2 + b] + (b ? gIF.y : gIF.x);
                const float gf = acc[mf][1][half * 2 + b] + (b ? gIF.w : gIF.z);
                const float gg = acc[mf][2][half * 2 + b] + (b ? gGO.y : gGO.x);
                const float go = acc[mf][3][half * 2 + b] + (b ? gGO.w : gGO.z);
                const float cv = sigmoid_f(gf) * (b ? cold.y : cold.x)
                               + sigmoid_f(gi) * tanh_f(gg);
                cn[b] = cv;
                hn[b] = sigmoid_f(go) * tanh_f(cv);
            }
            *(float2*)(cst + (size_t)r * H + jc) = make_float2(cn[0], cn[1]);
            hwrite[(size_t)r * HW + hwoff] = packh2(hn[0], hn[1]);
        }
}

// ============================================================================
// Fused FC: out = act(A1 @ W1^T + m @ W2^T + b), K = K1+K2 concat.
// ============================================================================
template <int K1, int K2, int NOUT, int BLKN, int LAYER>
__global__ __launch_bounds__(256, 2)
void mma_fc_k(const int* __restrict__ deg, const float* __restrict__ bias,
              float* __restrict__ outp, int n)
{
    const int r0 = blockIdx.x * 128;
    if (r0 >= n) return;
    const int n0 = blockIdx.y * BLKN;
    constexpr int NCH = (K1 + K2) / 16;
    constexpr int NCH1 = K1 / 16;
    constexpr int NFRW = BLKN / 32;
    constexpr int K1W = K1 / 2, K2W = K2 / 2;

    __shared__ __align__(16) u32 As[4][128][8];
    __shared__ __align__(16) u32 Bs[4][BLKN][8];
    constexpr u32 BUFSZ_A = 128 * 8 * 4;
    constexpr u32 BUFSZ_B = BLKN * 8 * 4;

    const u32* A1 = (LAYER == 1) ? d_featq : d_houtq;
    const u32* W1 = (LAYER == 1) ? d_Ws1q : d_Ws2q;
    const u32* W2 = (LAYER == 1) ? d_Wn1q : d_Wn2q;

    const int tid = threadIdx.x;
    const int w = tid >> 5, lane = tid & 31;
    const int q = lane >> 2, tig = lane & 3;
    const int wm = w >> 2, wn = w & 3;

    const int crow = tid >> 1;
    const int cseg = (tid & 1) * 4;
    int ra = r0 + crow; if (ra > n - 1) ra = n - 1;
    const u32* p1 = A1 + (size_t)ra * K1W + cseg;
    const u32* hb = (LAYER == 1) ? d_h1q[deg[ra] & 1] : d_h2q[deg[ra] & 1];
    const u32* p2 = hb + (size_t)d_rank[ra] * K2W + cseg;
    const bool bact = (tid < 2 * BLKN);
    const int bro = n0 + (crow & (BLKN - 1));
    const u32* q1 = W1 + (size_t)bro * K1W + cseg;
    const u32* q2 = W2 + (size_t)bro * K2W + cseg;

    const u32 asm0 = smem_u32(&As[0][crow][cseg]);
    const u32 bsm0 = smem_u32(&Bs[0][crow & (BLKN - 1)][cseg]);

    float acc[4][NFRW][4];
#pragma unroll
    for (int i = 0; i < 4; i++)
#pragma unroll
        for (int j = 0; j < NFRW; j++)
#pragma unroll
            for (int c = 0; c < 4; c++) acc[i][j][c] = 0.f;

    auto issue = [&](int chunk) {
        if (chunk < NCH) {
            const u32 offA = (chunk & 3) * BUFSZ_A;
            const u32 offB = (chunk & 3) * BUFSZ_B;
            const u32* srcA = (chunk < NCH1) ? (p1 + chunk * 8)
                                             : (p2 + (chunk - NCH1) * 8);
            cpa16(asm0 + offA, srcA);
            if (bact) {
                const u32* srcB = (chunk < NCH1) ? (q1 + chunk * 8)
                                                 : (q2 + (chunk - NCH1) * 8);
                cpa16(bsm0 + offB, srcB);
            }
        }
        cpa_commit();
    };
    issue(0); issue(1); issue(2);

#pragma unroll 1
    for (int c = 0; c < NCH; c++) {
        cpa_wait<2>();
        __syncthreads();
        issue(c + 3);
        mma_tile<NFRW>(As[c & 3], Bs[c & 3], acc, wm, wn, q, tig);
    }

    float2 bv2[NFRW];
#pragma unroll
    for (int nf = 0; nf < NFRW; nf++) {
        const int col = n0 + wn * (8 * NFRW) + nf * 8 + 2 * tig;
        bv2[nf] = make_float2(bias[col], bias[col + 1]);
    }
#pragma unroll
    for (int mf = 0; mf < 4; mf++)
#pragma unroll
        for (int half = 0; half < 2; half++) {
            const int r = r0 + wm * 64 + mf * 16 + q + half * 8;
            if (r >= n) continue;
#pragma unroll
            for (int nf = 0; nf < NFRW; nf++) {
                const int col = n0 + wn * (8 * NFRW) + nf * 8 + 2 * tig;
                float v0 = acc[mf][nf][half * 2]     + bv2[nf].x;
                float v1 = acc[mf][nf][half * 2 + 1] + bv2[nf].y;
                if (LAYER == 1) {
                    v0 = fmaxf(v0, 0.f); v1 = fmaxf(v1, 0.f);
                    const int cm = col & 15;
                    const int cw = (cm < 8) ? cm : cm - 7;
                    d_houtq[(size_t)r * (NOUT / 2) + ((col >> 4) << 3) + cw] =
                        packh2(v0, v1);
                } else {
                    *(float2*)(outp + (size_t)r * NOUT + col) = make_float2(v0, v1);
                }
            }
        }
}

// ---------------- launch ----------------------------------------------------
extern "C" void kernel_launch(void* const* d_in, const int* in_sizes, int n_in,
                              void* d_out, int out_size)
{
    const float* feat    = (const float*)d_in[0];
    const int*   nbr     = (const int*)d_in[1];
    const int*   deg     = (const int*)d_in[2];
    const float* Wih1    = (const float*)d_in[3];
    const float* Whh1    = (const float*)d_in[4];
    const float* bih1    = (const float*)d_in[5];
    const float* bhh1    = (const float*)d_in[6];
    const float* Wself1  = (const float*)d_in[7];
    const float* Wneigh1 = (const float*)d_in[8];
    const float* b1      = (const float*)d_in[9];
    const float* Wih2    = (const float*)d_in[10];
    const float* Whh2    = (const float*)d_in[11];
    const float* bih2    = (const float*)d_in[12];
    const float* bhh2    = (const float*)d_in[13];
    const float* Wself2  = (const float*)d_in[14];
    const float* Wneigh2 = (const float*)d_in[15];
    const float* b2      = (const float*)d_in[16];

    const int n  = in_sizes[2];           // = N
    const int rb = (n + 127) / 128;

    sort_zero_k<<<1, 32>>>();
    sort_hist_k<<<(n + 255) / 256, 256>>>(deg, n);
    sort_scan_k<<<1, 1>>>();
    sort_scatter_k<<<(n + 255) / 256, 256>>>(deg, n);

    convert_all_k<<<1024, 256>>>(feat, in_sizes[0], Wih1, in_sizes[3],
                                 Whh1, in_sizes[4], Wih2, in_sizes[10],
                                 Whh2, in_sizes[11], Wself1, in_sizes[7],
                                 Wneigh1, in_sizes[8], Wself2, in_sizes[14],
                                 Wneigh2, in_sizes[15]);

    // layer 1
    mma_gx_k<128, 1><<<dim3(rb, 4), 256>>>(bih1, bhh1, n);
    for (int t = 0; t < 16; t++)
        mma_lstm_k<128, 1><<<dim3(rb, 4), 256>>>(nbr, t, n);
    mma_fc_k<128, 128, 256, 128, 1><<<dim3(rb, 2), 256>>>(deg, b1, nullptr, n);

    // layer 2
    mma_gx_k<256, 2><<<dim3(rb, 8), 256>>>(bih2, bhh2, n);
    for (int t = 0; t < 16; t++)
        mma_lstm_k<256, 2><<<dim3(rb, 8), 256>>>(nbr, t, n);
    mma_fc_k<256, 256, 64, 64, 2><<<dim3(rb, 1), 256>>>(deg, b2,
                                                        (float*)d_out, n);
}